// round 15
// baseline (speedup 1.0000x reference)
#include <cuda_runtime.h>
#include <cstdint>

#define T_SEQ   2048
#define NH      16
#define HD      64
#define C_EMB   1024
#define BATCH   4
#define M_ROWS  (BATCH * T_SEQ)   // 8192

// Scratch (allocation-free rule: __device__ globals)
__device__ uint32_t g_Q[(size_t)M_ROWS * C_EMB];      // Q pre-scaled, tf32 bits
__device__ uint32_t g_K[(size_t)M_ROWS * C_EMB];      // tf32 bits
__device__ uint32_t g_V[(size_t)M_ROWS * C_EMB];      // tf32 bits
__device__ uint32_t g_X[(size_t)M_ROWS * C_EMB];      // x as tf32 bits
__device__ uint32_t g_Yatt[(size_t)M_ROWS * C_EMB];   // attention out, tf32 bits
__device__ uint32_t g_WT[4][(size_t)C_EMB * C_EMB];   // W^T as tf32 bits [N][K]

__device__ __forceinline__ uint32_t f2tf32(float x) {
    uint32_t r;
    asm("cvt.rna.tf32.f32 %0, %1;" : "=r"(r) : "f"(x));
    return r;
}

__device__ __forceinline__ void mma_tf32(float* c, const uint32_t* a, const uint32_t* b) {
    asm volatile(
        "mma.sync.aligned.m16n8k8.row.col.f32.tf32.tf32.f32 "
        "{%0,%1,%2,%3}, {%4,%5,%6,%7}, {%8,%9}, {%0,%1,%2,%3};"
        : "+f"(c[0]), "+f"(c[1]), "+f"(c[2]), "+f"(c[3])
        : "r"(a[0]), "r"(a[1]), "r"(a[2]), "r"(a[3]), "r"(b[0]), "r"(b[1]));
}

__device__ __forceinline__ void ldsm_x4(uint32_t* r, uint32_t addr) {
    asm volatile(
        "ldmatrix.sync.aligned.m8n8.x4.shared.b16 {%0,%1,%2,%3}, [%4];"
        : "=r"(r[0]), "=r"(r[1]), "=r"(r[2]), "=r"(r[3]) : "r"(addr));
}

__device__ __forceinline__ uint32_t smem_u32(const void* p) {
    return (uint32_t)__cvta_generic_to_shared(p);
}

#define CP_ASYNC16(dst, src) \
    asm volatile("cp.async.ca.shared.global [%0], [%1], 16;" :: "r"(dst), "l"(src) : "memory")
#define CP_COMMIT() asm volatile("cp.async.commit_group;" ::: "memory")
#define CP_WAIT0()  asm volatile("cp.async.wait_group 0;" ::: "memory")
#define CP_WAIT1()  asm volatile("cp.async.wait_group 1;" ::: "memory")

// ---------------------------------------------------------------------------
// x -> tf32 bits (one pass)
// ---------------------------------------------------------------------------
__global__ __launch_bounds__(256) void convert_x(
    const float* __restrict__ x, uint32_t* __restrict__ o)
{
    const size_t i = ((size_t)blockIdx.x * 256 + threadIdx.x) * 4;
    const float4 v = *(const float4*)(x + i);
    *(uint4*)(o + i) = make_uint4(f2tf32(v.x), f2tf32(v.y), f2tf32(v.z), f2tf32(v.w));
}

// ---------------------------------------------------------------------------
// Weight transpose + tf32 convert: WT[z][n*K+k] = tf32(W_z[k*N+n])
// ---------------------------------------------------------------------------
__global__ __launch_bounds__(256) void transpose_w(
    const float* __restrict__ W0, const float* __restrict__ W1,
    const float* __restrict__ W2, const float* __restrict__ W3,
    uint32_t* __restrict__ WT)
{
    __shared__ float tile[32][33];
    const float* W = (blockIdx.z == 0) ? W0 : (blockIdx.z == 1) ? W1
                   : (blockIdx.z == 2) ? W2 : W3;
    uint32_t* out = WT + (size_t)blockIdx.z * C_EMB * C_EMB;

    const int x = threadIdx.x & 31;
    const int y0 = (threadIdx.x >> 5) << 2;
    const int kb = blockIdx.x * 32, nb = blockIdx.y * 32;
#pragma unroll
    for (int i = 0; i < 4; i++)
        tile[y0 + i][x] = W[(size_t)(kb + y0 + i) * C_EMB + nb + x];
    __syncthreads();
#pragma unroll
    for (int i = 0; i < 4; i++)
        out[(size_t)(nb + y0 + i) * C_EMB + kb + x] = f2tf32(tile[x][y0 + i]);
}

// ---------------------------------------------------------------------------
// mma.sync tf32 GEMM: C[M,N] = A[M,K](tf32 bits) @ BT[N,K](tf32 bits)^T + bias
// 128x128x16 CTA tile, 128 threads (4 warps, 2x2), warp tile 64x64.
// cp.async staging, double buffer, ldmatrix.x4 for both operands.
// MODE 0: float out, row-major [M,N].
// MODE 1: uint32 tf32-bits out, scaled, QKV scatter to [B,H,T,D].
// ---------------------------------------------------------------------------
#define BM 128
#define BN 128
#define BK 16
#define ASTRIDE 20   // words per row (16 k + 4 pad) -> conflict-free LDSM + cp.async

template <int MODE>
__device__ __forceinline__ void gemm_body(
    const uint32_t* __restrict__ A, const uint32_t* __restrict__ BT,
    const float* __restrict__ bias, float* __restrict__ CoutF,
    uint32_t* __restrict__ CoutU, float scale)
{
    __shared__ uint32_t SA[2][BM * ASTRIDE];
    __shared__ uint32_t SB[2][BN * ASTRIDE];

    const int tid  = threadIdx.x;      // 0..127
    const int wid  = tid >> 5;
    const int lane = tid & 31;
    const int g    = lane >> 2;
    const int tig  = lane & 3;
    const int bm   = blockIdx.y * BM;
    const int bn   = blockIdx.x * BN;
    const int wm   = (wid & 1) * 64;
    const int wn   = (wid >> 1) * 64;

    const uint32_t sa[2] = { smem_u32(&SA[0][0]), smem_u32(&SA[1][0]) };
    const uint32_t sb[2] = { smem_u32(&SB[0][0]), smem_u32(&SB[1][0]) };
    const uint32_t lane_off = (((lane & 15) * ASTRIDE) + ((lane >> 4) << 2)) * 4;

    float acc[4][8][4];
#pragma unroll
    for (int i = 0; i < 4; i++)
#pragma unroll
        for (int j = 0; j < 8; j++)
#pragma unroll
            for (int r = 0; r < 4; r++) acc[i][j][r] = 0.f;

#define ISSUE_TILE(bf, k0)                                                     \
    do {                                                                       \
        _Pragma("unroll")                                                      \
        for (int r = 0; r < 4; r++) {                                          \
            const int idx = tid + r * 128;                                     \
            const int row = idx >> 2;                                          \
            const int kq  = (idx & 3) << 2;                                    \
            CP_ASYNC16(sa[bf] + (uint32_t)((row * ASTRIDE + kq) * 4),          \
                       A + (size_t)(bm + row) * C_EMB + (k0) + kq);            \
            CP_ASYNC16(sb[bf] + (uint32_t)((row * ASTRIDE + kq) * 4),          \
                       BT + (size_t)(bn + row) * C_EMB + (k0) + kq);           \
        }                                                                      \
    } while (0)

    ISSUE_TILE(0, 0);
    CP_COMMIT();

    const int NCH = C_EMB / BK;   // 64
    for (int c = 0; c < NCH; c++) {
        const int buf = c & 1;
        CP_WAIT0();
        __syncthreads();
        if (c + 1 < NCH) {
            ISSUE_TILE(buf ^ 1, (c + 1) * BK);
            CP_COMMIT();
        }

#pragma unroll
        for (int ks = 0; ks < BK; ks += 8) {
            uint32_t af[4][4], bl[4][4];
#pragma unroll
            for (int i = 0; i < 4; i++)
                ldsm_x4(af[i], sa[buf] + lane_off +
                               (uint32_t)(((wm + 16 * i) * ASTRIDE + ks) * 4));
#pragma unroll
            for (int p = 0; p < 4; p++)
                ldsm_x4(bl[p], sb[buf] + lane_off +
                               (uint32_t)(((wn + 16 * p) * ASTRIDE + ks) * 4));
#pragma unroll
            for (int i = 0; i < 4; i++)
#pragma unroll
                for (int j = 0; j < 8; j++) {
                    uint32_t b[2] = { bl[j >> 1][j & 1], bl[j >> 1][2 + (j & 1)] };
                    mma_tf32(acc[i][j], af[i], b);
                }
        }
    }
#undef ISSUE_TILE

#pragma unroll
    for (int j = 0; j < 8; j++) {
        const int col = bn + wn + 8 * j + 2 * tig;
        const float b0 = bias[col];
        const float b1 = bias[col + 1];
#pragma unroll
        for (int i = 0; i < 4; i++) {
            const int row = bm + wm + 16 * i + g;
            if (MODE == 0) {
                const float2 v0 = make_float2(acc[i][j][0] + b0, acc[i][j][1] + b1);
                const float2 v1 = make_float2(acc[i][j][2] + b0, acc[i][j][3] + b1);
                *(float2*)&CoutF[(size_t)row * C_EMB + col] = v0;
                *(float2*)&CoutF[(size_t)(row + 8) * C_EMB + col] = v1;
            } else {
                const uint2 v0 = make_uint2(f2tf32((acc[i][j][0] + b0) * scale),
                                            f2tf32((acc[i][j][1] + b1) * scale));
                const uint2 v1 = make_uint2(f2tf32((acc[i][j][2] + b0) * scale),
                                            f2tf32((acc[i][j][3] + b1) * scale));
                const int h_ = col >> 6;
                const int d_ = col & (HD - 1);
                const int b0_ = row >> 11;
                const int t0_ = row & (T_SEQ - 1);
                const int b1_ = (row + 8) >> 11;
                const int t1_ = (row + 8) & (T_SEQ - 1);
                *(uint2*)&CoutU[(((size_t)b0_ * NH + h_) * T_SEQ + t0_) * HD + d_] = v0;
                *(uint2*)&CoutU[(((size_t)b1_ * NH + h_) * T_SEQ + t1_) * HD + d_] = v1;
            }
        }
    }
}

__global__ __launch_bounds__(128) void gemm_qkv(
    const uint32_t* __restrict__ A, const uint32_t* __restrict__ WT,
    const float* __restrict__ c0, const float* __restrict__ c1,
    const float* __restrict__ c2,
    uint32_t* __restrict__ O0, uint32_t* __restrict__ O1, uint32_t* __restrict__ O2)
{
    const int z = blockIdx.z;
    const uint32_t* BT = WT + (size_t)z * C_EMB * C_EMB;
    const float* bias  = (z == 0) ? c0 : (z == 1) ? c1 : c2;
    uint32_t* Cout     = (z == 0) ? O0 : (z == 1) ? O1 : O2;
    const float scale  = (z == 0) ? 0.125f : 1.0f;   // fold 1/sqrt(D) into Q
    gemm_body<1>(A, BT, bias, nullptr, Cout, scale);
}

__global__ __launch_bounds__(128) void gemm_out(
    const uint32_t* __restrict__ A, const uint32_t* __restrict__ WT,
    const float* __restrict__ bias, float* __restrict__ Cout)
{
    gemm_body<0>(A, WT + (size_t)3 * C_EMB * C_EMB, bias, Cout, nullptr, 1.0f);
}

// ---------------------------------------------------------------------------
// Tensor-core flash attention (tf32 mma.sync, fp32 softmax/accum, causal).
// 128 queries/CTA, 64-key tiles, 8 warps x 16 query rows each.
// Q/K/V arrive as tf32 bits; staging = cp.async; K/V double-buffered.
// ---------------------------------------------------------------------------
#define QS_STRIDE 68
#define KS_STRIDE 68
#define VS_STRIDE 72
#define KV_WORDS  (64 * KS_STRIDE + 64 * VS_STRIDE)
#define ATTN_SMEM ((128 * QS_STRIDE + 2 * KV_WORDS) * 4)   // 106496 B

__global__ __launch_bounds__(256, 2) void attn_tc_kernel(
    const uint32_t* __restrict__ Q, const uint32_t* __restrict__ K,
    const uint32_t* __restrict__ V, uint32_t* __restrict__ Y)
{
    extern __shared__ uint32_t smu[];
    uint32_t* Qsm = smu;                                  // [128][68]
    uint32_t* Kw[2] = { smu + 128 * QS_STRIDE,
                        smu + 128 * QS_STRIDE + KV_WORDS };
    const uint32_t sQ = smem_u32(Qsm);
    const uint32_t sK[2] = { smem_u32(Kw[0]), smem_u32(Kw[1]) };

    const int tid  = threadIdx.x;
    const int w    = tid >> 5;
    const int lane = tid & 31;
    const int g    = lane >> 2;
    const int tig  = lane & 3;
    const int bh   = blockIdx.y;
    const int qb   = blockIdx.x;
    const int q0   = qb * 128;

    const uint32_t* Qg = Q + ((size_t)bh * T_SEQ + q0) * HD;
    const uint32_t* Kg = K + (size_t)bh * T_SEQ * HD;
    const uint32_t* Vg = V + (size_t)bh * T_SEQ * HD;

#define ISSUE_KV(bf, s0_)                                                      \
    do {                                                                       \
        _Pragma("unroll")                                                      \
        for (int r = 0; r < 4; r++) {                                          \
            const int idx = tid + r * 256;                                     \
            const int row = idx >> 4;                                          \
            const int d4  = (idx & 15) << 2;                                   \
            CP_ASYNC16(sK[bf] + (uint32_t)((row * KS_STRIDE + d4) * 4),        \
                       Kg + (size_t)((s0_) + row) * HD + d4);                  \
            CP_ASYNC16(sK[bf] + (uint32_t)(64 * KS_STRIDE * 4)                 \
                              + (uint32_t)((row * VS_STRIDE + d4) * 4),        \
                       Vg + (size_t)((s0_) + row) * HD + d4);                  \
        }                                                                      \
    } while (0)

    // prologue: Q + tile 0 as group 0
#pragma unroll
    for (int r = 0; r < 8; r++) {
        const int idx = tid + r * 256;
        const int row = idx >> 4;
        const int d4  = (idx & 15) << 2;
        CP_ASYNC16(sQ + (uint32_t)((row * QS_STRIDE + d4) * 4),
                   Qg + (size_t)row * HD + d4);
    }
    ISSUE_KV(0, 0);
    CP_COMMIT();

    float o[8][4];
#pragma unroll
    for (int j = 0; j < 8; j++)
#pragma unroll
        for (int r = 0; r < 4; r++) o[j][r] = 0.f;
    float m_lo = -1e30f, m_hi = -1e30f, l_lo = 0.f, l_hi = 0.f;

    const int r0      = 16 * w + g;
    const int row_lo  = q0 + r0;
    const int row_hi  = row_lo + 8;
    const int row_max_w = q0 + 16 * w + 15;
    const int qbase = lane & 28;
    const int srcA  = qbase + (tig >> 1);
    const int srcB  = srcA + 2;

    const int ntiles = 2 * qb + 2;
    for (int c = 0; c < ntiles; c++) {
        const int buf = c & 1;
        const int s0  = c * 64;
        if (c + 1 < ntiles) {
            ISSUE_KV(buf ^ 1, s0 + 64);
            CP_COMMIT();
            CP_WAIT1();
        } else {
            CP_WAIT0();
        }
        __syncthreads();

        if (s0 <= row_max_w) {
            const uint32_t* Ksm = Kw[buf];
            const uint32_t* Vsm = Kw[buf] + 64 * KS_STRIDE;

            float s_[8][4];
#pragma unroll
            for (int j = 0; j < 8; j++)
#pragma unroll
                for (int r = 0; r < 4; r++) s_[j][r] = 0.f;

#pragma unroll
            for (int ks = 0; ks < 8; ks++) {
                uint32_t a[4];
                a[0] = Qsm[r0 * QS_STRIDE + 8 * ks + tig];
                a[1] = Qsm[(r0 + 8) * QS_STRIDE + 8 * ks + tig];
                a[2] = Qsm[r0 * QS_STRIDE + 8 * ks + tig + 4];
                a[3] = Qsm[(r0 + 8) * QS_STRIDE + 8 * ks + tig + 4];
#pragma unroll
                for (int j = 0; j < 8; j++) {
                    uint32_t b[2];
                    b[0] = Ksm[(8 * j + g) * KS_STRIDE + 8 * ks + tig];
                    b[1] = Ksm[(8 * j + g) * KS_STRIDE + 8 * ks + tig + 4];
                    mma_tf32(s_[j], a, b);
                }
            }

            if (s0 + 63 > q0 + 16 * w) {
#pragma unroll
                for (int j = 0; j < 8; j++) {
                    const int c0 = s0 + 8 * j + 2 * tig;
                    if (c0 > row_lo)     s_[j][0] = -1e30f;
                    if (c0 + 1 > row_lo) s_[j][1] = -1e30f;
                    if (c0 > row_hi)     s_[j][2] = -1e30f;
                    if (c0 + 1 > row_hi) s_[j][3] = -1e30f;
                }
            }

            float t_lo = -1e30f, t_hi = -1e30f;
#pragma unroll
            for (int j = 0; j < 8; j++) {
                t_lo = fmaxf(t_lo, fmaxf(s_[j][0], s_[j][1]));
                t_hi = fmaxf(t_hi, fmaxf(s_[j][2], s_[j][3]));
            }
            t_lo = fmaxf(t_lo, __shfl_xor_sync(0xffffffffu, t_lo, 1));
            t_lo = fmaxf(t_lo, __shfl_xor_sync(0xffffffffu, t_lo, 2));
            t_hi = fmaxf(t_hi, __shfl_xor_sync(0xffffffffu, t_hi, 1));
            t_hi = fmaxf(t_hi, __shfl_xor_sync(0xffffffffu, t_hi, 2));

            const float mn_lo = fmaxf(m_lo, t_lo);
            const float mn_hi = fmaxf(m_hi, t_hi);
            const float a_lo = __expf(m_lo - mn_lo);
            const float a_hi = __expf(m_hi - mn_hi);
            m_lo = mn_lo; m_hi = mn_hi;

            float rs_lo = 0.f, rs_hi = 0.f;
#pragma unroll
            for (int j = 0; j < 8; j++) {
                const float p0 = __expf(s_[j][0] - mn_lo);
                const float p1 = __expf(s_[j][1] - mn_lo);
                const float p2 = __expf(s_[j][2] - mn_hi);
                const float p3 = __expf(s_[j][3] - mn_hi);
                rs_lo += p0 + p1;
                rs_hi += p2 + p3;
                s_[j][0] = __uint_as_float(f2tf32(p0));
                s_[j][1] = __uint_as_float(f2tf32(p1));
                s_[j][2] = __uint_as_float(f2tf32(p2));
                s_[j][3] = __uint_as_float(f2tf32(p3));
            }
            rs_lo += __shfl_xor_sync(0xffffffffu, rs_lo, 1);
            rs_lo += __shfl_xor_sync(0xffffffffu, rs_lo, 2);
            rs_hi += __shfl_xor_sync(0xffffffffu, rs_hi, 1);
            rs_hi += __shfl_xor_sync(0xffffffffu, rs_hi, 2);
            l_lo = l_lo * a_lo + rs_lo;
            l_hi = l_hi * a_hi + rs_hi;

#pragma unroll
            for (int jd = 0; jd < 8; jd++) {
                o[jd][0] *= a_lo; o[jd][1] *= a_lo;
                o[jd][2] *= a_hi; o[jd][3] *= a_hi;
            }

#pragma unroll
            for (int ks = 0; ks < 8; ks++) {
                const float p0 = s_[ks][0], p1 = s_[ks][1];
                const float p2 = s_[ks][2], p3 = s_[ks][3];
                const float u0 = __shfl_sync(0xffffffffu, p0, srcA);
                const float u1 = __shfl_sync(0xffffffffu, p1, srcA);
                const float v0 = __shfl_sync(0xffffffffu, p2, srcA);
                const float v1 = __shfl_sync(0xffffffffu, p3, srcA);
                const float x0 = __shfl_sync(0xffffffffu, p0, srcB);
                const float x1 = __shfl_sync(0xffffffffu, p1, srcB);
                const float y0 = __shfl_sync(0xffffffffu, p2, srcB);
                const float y1 = __shfl_sync(0xffffffffu, p3, srcB);
                uint32_t a[4];
                a[0] = __float_as_uint((tig & 1) ? u1 : u0);
                a[1] = __float_as_uint((tig & 1) ? v1 : v0);
                a[2] = __float_as_uint((tig & 1) ? x1 : x0);
                a[3] = __float_as_uint((tig & 1) ? y1 : y0);
#pragma unroll
                for (int jd = 0; jd < 8; jd++) {
                    uint32_t b[2];
                    b[0] = Vsm[(8 * ks + tig) * VS_STRIDE + 8 * jd + g];
                    b[1] = Vsm[(8 * ks + tig + 4) * VS_STRIDE + 8 * jd + g];
                    mma_tf32(o[jd], a, b);
                }
            }
        }
        __syncthreads();
    }
#undef ISSUE_KV

    const float il_lo = 1.0f / l_lo;
    const float il_hi = 1.0f / l_hi;
    const int b_ = bh >> 4;
    const int h_ = bh & 15;
    uint32_t* Yb = Y + (size_t)b_ * T_SEQ * C_EMB + h_ * HD;
#pragma unroll
    for (int jd = 0; jd < 8; jd++) {
        const int d = 8 * jd + 2 * tig;
        const uint2 vlo = make_uint2(f2tf32(o[jd][0] * il_lo), f2tf32(o[jd][1] * il_lo));
        const uint2 vhi = make_uint2(f2tf32(o[jd][2] * il_hi), f2tf32(o[jd][3] * il_hi));
        *(uint2*)&Yb[(size_t)row_lo * C_EMB + d] = vlo;
        *(uint2*)&Yb[(size_t)row_hi * C_EMB + d] = vhi;
    }
}

// ---------------------------------------------------------------------------
extern "C" void kernel_launch(void* const* d_in, const int* in_sizes, int n_in,
                              void* d_out, int out_size)
{
    const float* x  = (const float*)d_in[0];
    const float* Wq = (const float*)d_in[1];
    const float* bq = (const float*)d_in[2];
    const float* Wk = (const float*)d_in[3];
    const float* bk = (const float*)d_in[4];
    const float* Wv = (const float*)d_in[5];
    const float* bv = (const float*)d_in[6];
    const float* Wp = (const float*)d_in[7];
    const float* bp = (const float*)d_in[8];
    float* out = (float*)d_out;

    uint32_t *Qp, *Kp, *Vp, *Xp, *Yp, *WTp;
    cudaGetSymbolAddress((void**)&Qp, g_Q);
    cudaGetSymbolAddress((void**)&Kp, g_K);
    cudaGetSymbolAddress((void**)&Vp, g_V);
    cudaGetSymbolAddress((void**)&Xp, g_X);
    cudaGetSymbolAddress((void**)&Yp, g_Yatt);
    cudaGetSymbolAddress((void**)&WTp, g_WT);

    cudaFuncSetAttribute(attn_tc_kernel,
                         cudaFuncAttributeMaxDynamicSharedMemorySize, ATTN_SMEM);

    convert_x<<<(M_ROWS * C_EMB) / 1024, 256>>>(x, Xp);
    transpose_w<<<dim3(32, 32, 4), 256>>>(Wq, Wk, Wv, Wp, WTp);

    gemm_qkv<<<dim3(C_EMB / BN, M_ROWS / BM, 3), 128>>>(Xp, WTp, bq, bk, bv,
                                                        Qp, Kp, Vp);

    attn_tc_kernel<<<dim3(T_SEQ / 128, BATCH * NH), 256, ATTN_SMEM>>>(Qp, Kp, Vp, Yp);

    gemm_out<<<dim3(C_EMB / BN, M_ROWS / BM), 128>>>(Yp, WTp, bp, out);
}

// round 16
// speedup vs baseline: 2.1369x; 2.1369x over previous
#include <cuda_runtime.h>
#include <cuda_fp16.h>
#include <cstdint>

#define T_SEQ   2048
#define NH      16
#define HD      64
#define C_EMB   1024
#define BATCH   4
#define M_ROWS  (BATCH * T_SEQ)   // 8192

// Scratch (allocation-free rule: __device__ globals) — all fp16
__device__ __half g_Q[(size_t)M_ROWS * C_EMB];      // Q pre-scaled by 1/8
__device__ __half g_K[(size_t)M_ROWS * C_EMB];
__device__ __half g_V[(size_t)M_ROWS * C_EMB];
__device__ __half g_X[(size_t)M_ROWS * C_EMB];
__device__ __half g_Yatt[(size_t)M_ROWS * C_EMB];
__device__ __half g_WT[4][(size_t)C_EMB * C_EMB];   // W^T [N][K]

__device__ __forceinline__ uint32_t pack_h2(float lo, float hi) {
    __half2 h = __floats2half2_rn(lo, hi);
    return *reinterpret_cast<uint32_t*>(&h);
}

__device__ __forceinline__ void mma_f16(float* c, const uint32_t* a,
                                        uint32_t b0, uint32_t b1) {
    asm volatile(
        "mma.sync.aligned.m16n8k16.row.col.f32.f16.f16.f32 "
        "{%0,%1,%2,%3}, {%4,%5,%6,%7}, {%8,%9}, {%0,%1,%2,%3};"
        : "+f"(c[0]), "+f"(c[1]), "+f"(c[2]), "+f"(c[3])
        : "r"(a[0]), "r"(a[1]), "r"(a[2]), "r"(a[3]), "r"(b0), "r"(b1));
}

__device__ __forceinline__ void ldsm_x4(uint32_t* r, uint32_t addr) {
    asm volatile(
        "ldmatrix.sync.aligned.m8n8.x4.shared.b16 {%0,%1,%2,%3}, [%4];"
        : "=r"(r[0]), "=r"(r[1]), "=r"(r[2]), "=r"(r[3]) : "r"(addr));
}
__device__ __forceinline__ void ldsm_x4_t(uint32_t* r, uint32_t addr) {
    asm volatile(
        "ldmatrix.sync.aligned.m8n8.x4.trans.shared.b16 {%0,%1,%2,%3}, [%4];"
        : "=r"(r[0]), "=r"(r[1]), "=r"(r[2]), "=r"(r[3]) : "r"(addr));
}

__device__ __forceinline__ uint32_t smem_u32(const void* p) {
    return (uint32_t)__cvta_generic_to_shared(p);
}

#define CP_ASYNC16(dst, src) \
    asm volatile("cp.async.ca.shared.global [%0], [%1], 16;" :: "r"(dst), "l"(src) : "memory")
#define CP_COMMIT() asm volatile("cp.async.commit_group;" ::: "memory")
#define CP_WAIT0()  asm volatile("cp.async.wait_group 0;" ::: "memory")

// ---------------------------------------------------------------------------
// x -> half (one pass)
// ---------------------------------------------------------------------------
__global__ __launch_bounds__(256) void convert_x(
    const float* __restrict__ x, __half* __restrict__ o)
{
    const size_t i = ((size_t)blockIdx.x * 256 + threadIdx.x) * 4;
    const float4 v = *(const float4*)(x + i);
    uint2 u;
    u.x = pack_h2(v.x, v.y);
    u.y = pack_h2(v.z, v.w);
    *(uint2*)(o + i) = u;
}

// ---------------------------------------------------------------------------
// Weight transpose + half convert: WT[z][n*K+k] = half(W_z[k*N+n])
// ---------------------------------------------------------------------------
__global__ __launch_bounds__(256) void transpose_w(
    const float* __restrict__ W0, const float* __restrict__ W1,
    const float* __restrict__ W2, const float* __restrict__ W3,
    __half* __restrict__ WT)
{
    __shared__ float tile[32][33];
    const float* W = (blockIdx.z == 0) ? W0 : (blockIdx.z == 1) ? W1
                   : (blockIdx.z == 2) ? W2 : W3;
    __half* out = WT + (size_t)blockIdx.z * C_EMB * C_EMB;

    const int x = threadIdx.x & 31;
    const int y0 = (threadIdx.x >> 5) << 2;
    const int kb = blockIdx.x * 32, nb = blockIdx.y * 32;
#pragma unroll
    for (int i = 0; i < 4; i++)
        tile[y0 + i][x] = W[(size_t)(kb + y0 + i) * C_EMB + nb + x];
    __syncthreads();
#pragma unroll
    for (int i = 0; i < 4; i++)
        out[(size_t)(nb + y0 + i) * C_EMB + kb + x] = __float2half_rn(tile[x][y0 + i]);
}

// ---------------------------------------------------------------------------
// fp16 GEMM: C[M,N] = A[M,K] @ BT[N,K]^T + bias, m16n8k16, fp32 accum.
// 128x128x32 CTA tile, 128 threads (4 warps 2x2), warp tile 64x64.
// Smem rows 40 halves (80B) -> ldmatrix rows tile banks perfectly.
// MODE 0: float out row-major. MODE 1: half out, scaled, QKV scatter.
// ---------------------------------------------------------------------------
#define BKH 32     // k halves per tile
#define STRH 40    // halves per smem row (32 + 8 pad) = 80 bytes

template <int MODE>
__device__ __forceinline__ void gemm_body(
    const __half* __restrict__ A, const __half* __restrict__ BT,
    const float* __restrict__ bias, float* __restrict__ CoutF,
    __half* __restrict__ CoutH, float scale)
{
    __shared__ __half SA[2][128 * STRH];
    __shared__ __half SB[2][128 * STRH];

    const int tid  = threadIdx.x;
    const int wid  = tid >> 5;
    const int lane = tid & 31;
    const int g    = lane >> 2;
    const int tig  = lane & 3;
    const int bm   = blockIdx.y * 128;
    const int bn   = blockIdx.x * 128;
    const int wm   = (wid & 1) * 64;
    const int wn   = (wid >> 1) * 64;

    const uint32_t sa[2] = { smem_u32(&SA[0][0]), smem_u32(&SA[1][0]) };
    const uint32_t sb[2] = { smem_u32(&SB[0][0]), smem_u32(&SB[1][0]) };
    // A frag rows: lane&15 ; +16B for k+8 halves (lane>=16)
    const uint32_t a_lane = (uint32_t)((lane & 15) * (STRH * 2) + ((lane >> 4) << 4));
    // B frag rows: (lane>>4)*8 + (lane&7) ; +16B if (lane>>3)&1
    const uint32_t b_lane = (uint32_t)((((lane >> 4) << 3) + (lane & 7)) * (STRH * 2)
                                       + (((lane >> 3) & 1) << 4));

    float acc[4][8][4];
#pragma unroll
    for (int i = 0; i < 4; i++)
#pragma unroll
        for (int j = 0; j < 8; j++)
#pragma unroll
            for (int r = 0; r < 4; r++) acc[i][j][r] = 0.f;

#define ISSUE_TILE(bf, k0)                                                     \
    do {                                                                       \
        _Pragma("unroll")                                                      \
        for (int r = 0; r < 4; r++) {                                          \
            const int idx = tid + r * 128;                                     \
            const int row = idx >> 2;                                          \
            const int ch  = idx & 3;                                           \
            CP_ASYNC16(sa[bf] + (uint32_t)(row * (STRH * 2) + ch * 16),        \
                       A + (size_t)(bm + row) * C_EMB + (k0) + ch * 8);        \
            CP_ASYNC16(sb[bf] + (uint32_t)(row * (STRH * 2) + ch * 16),        \
                       BT + (size_t)(bn + row) * C_EMB + (k0) + ch * 8);       \
        }                                                                      \
    } while (0)

    ISSUE_TILE(0, 0);
    CP_COMMIT();

    const int NCH = C_EMB / BKH;   // 32
    for (int c = 0; c < NCH; c++) {
        const int buf = c & 1;
        CP_WAIT0();
        __syncthreads();
        if (c + 1 < NCH) {
            ISSUE_TILE(buf ^ 1, (c + 1) * BKH);
            CP_COMMIT();
        }

#pragma unroll
        for (int kc = 0; kc < 2; kc++) {   // k-chunks of 16 halves
            uint32_t af[4][4], bl[4][4];
#pragma unroll
            for (int i = 0; i < 4; i++)
                ldsm_x4(af[i], sa[buf] + a_lane +
                               (uint32_t)(((wm + 16 * i) * STRH + kc * 16) * 2));
#pragma unroll
            for (int p = 0; p < 4; p++)
                ldsm_x4(bl[p], sb[buf] + b_lane +
                               (uint32_t)(((wn + 16 * p) * STRH + kc * 16) * 2));
#pragma unroll
            for (int i = 0; i < 4; i++)
#pragma unroll
                for (int j = 0; j < 8; j++)
                    mma_f16(acc[i][j], af[i],
                            bl[j >> 1][(j & 1) * 2], bl[j >> 1][(j & 1) * 2 + 1]);
        }
    }
#undef ISSUE_TILE

#pragma unroll
    for (int j = 0; j < 8; j++) {
        const int col = bn + wn + 8 * j + 2 * tig;
        const float b0 = bias[col];
        const float b1 = bias[col + 1];
#pragma unroll
        for (int i = 0; i < 4; i++) {
            const int row = bm + wm + 16 * i + g;
            if (MODE == 0) {
                *(float2*)&CoutF[(size_t)row * C_EMB + col] =
                    make_float2(acc[i][j][0] + b0, acc[i][j][1] + b1);
                *(float2*)&CoutF[(size_t)(row + 8) * C_EMB + col] =
                    make_float2(acc[i][j][2] + b0, acc[i][j][3] + b1);
            } else {
                const uint32_t v0 = pack_h2((acc[i][j][0] + b0) * scale,
                                            (acc[i][j][1] + b1) * scale);
                const uint32_t v1 = pack_h2((acc[i][j][2] + b0) * scale,
                                            (acc[i][j][3] + b1) * scale);
                const int h_ = col >> 6;
                const int d_ = col & (HD - 1);
                const int b0_ = row >> 11;
                const int t0_ = row & (T_SEQ - 1);
                const int b1_ = (row + 8) >> 11;
                const int t1_ = (row + 8) & (T_SEQ - 1);
                *(uint32_t*)&CoutH[(((size_t)b0_ * NH + h_) * T_SEQ + t0_) * HD + d_] = v0;
                *(uint32_t*)&CoutH[(((size_t)b1_ * NH + h_) * T_SEQ + t1_) * HD + d_] = v1;
            }
        }
    }
}

__global__ __launch_bounds__(128) void gemm_qkv(
    const __half* __restrict__ A, const __half* __restrict__ WT,
    const float* __restrict__ c0, const float* __restrict__ c1,
    const float* __restrict__ c2,
    __half* __restrict__ O0, __half* __restrict__ O1, __half* __restrict__ O2)
{
    const int z = blockIdx.z;
    const __half* BT  = WT + (size_t)z * C_EMB * C_EMB;
    const float* bias = (z == 0) ? c0 : (z == 1) ? c1 : c2;
    __half* Cout      = (z == 0) ? O0 : (z == 1) ? O1 : O2;
    const float scale = (z == 0) ? 0.125f : 1.0f;
    gemm_body<1>(A, BT, bias, nullptr, Cout, scale);
}

__global__ __launch_bounds__(128) void gemm_out(
    const __half* __restrict__ A, const __half* __restrict__ WT,
    const float* __restrict__ bias, float* __restrict__ Cout)
{
    gemm_body<0>(A, WT + (size_t)3 * C_EMB * C_EMB, bias, Cout, nullptr, 1.0f);
}

// ---------------------------------------------------------------------------
// fp16 flash attention (m16n8k16, fp32 softmax/accum, causal).
// 128 queries/CTA, 64-key tiles, 8 warps x 16 query rows. R13-style staging.
// V consumed via trans-ldmatrix (no transpose staging); P via register packs.
// ---------------------------------------------------------------------------
#define AQSTR 72   // halves per row (64 + 8) = 144 B
#define ATTN_SMEM ((128 * AQSTR + 64 * AQSTR + 64 * AQSTR) * 2)   // 36864 B

__global__ __launch_bounds__(256, 2) void attn_f16_kernel(
    const __half* __restrict__ Q, const __half* __restrict__ K,
    const __half* __restrict__ V, __half* __restrict__ Y)
{
    extern __shared__ __half smh[];
    __half* Qsm = smh;                    // [128][72]
    __half* Ksm = smh + 128 * AQSTR;      // [64][72]
    __half* Vsm = Ksm + 64 * AQSTR;       // [64][72]
    const uint32_t sQ = smem_u32(Qsm);
    const uint32_t sK = smem_u32(Ksm);
    const uint32_t sV = smem_u32(Vsm);

    const int tid  = threadIdx.x;
    const int w    = tid >> 5;
    const int lane = tid & 31;
    const int g    = lane >> 2;
    const int tig  = lane & 3;
    const int bh   = blockIdx.y;
    const int qb   = blockIdx.x;
    const int q0   = qb * 128;

    const __half* Qg = Q + ((size_t)bh * T_SEQ + q0) * HD;
    const __half* Kg = K + (size_t)bh * T_SEQ * HD;
    const __half* Vg = V + (size_t)bh * T_SEQ * HD;

    // ldmatrix lane offsets (bytes)
    const uint32_t q_lane = (uint32_t)((lane & 15) * (AQSTR * 2) + ((lane >> 4) << 4));
    const uint32_t k_lane = (uint32_t)((((lane >> 4) << 3) + (lane & 7)) * (AQSTR * 2)
                                       + (((lane >> 3) & 1) << 4));
    const uint32_t v_lane = (uint32_t)(((((lane >> 3) & 1) << 3) + (lane & 7)) * (AQSTR * 2)
                                       + ((lane >> 4) << 4));

    // Stage Q (uint4 copies; data already half)
#pragma unroll
    for (int r = 0; r < 4; r++) {
        const int idx = tid + r * 256;       // 1024 chunks
        const int row = idx >> 3;
        const int c8  = (idx & 7) << 3;      // halves
        *(uint4*)&Qsm[row * AQSTR + c8] = *(const uint4*)(Qg + (size_t)row * HD + c8);
    }

    float o[8][4];
#pragma unroll
    for (int j = 0; j < 8; j++)
#pragma unroll
        for (int r = 0; r < 4; r++) o[j][r] = 0.f;
    float m_lo = -1e30f, m_hi = -1e30f, l_lo = 0.f, l_hi = 0.f;

    const int row_lo  = q0 + 16 * w + g;
    const int row_hi  = row_lo + 8;
    const int row_max_w = q0 + 16 * w + 15;

    for (int s0 = 0; s0 < q0 + 128; s0 += 64) {
        __syncthreads();
#pragma unroll
        for (int r = 0; r < 2; r++) {
            const int idx = tid + r * 256;   // 512 chunks each
            const int row = idx >> 3;
            const int c8  = (idx & 7) << 3;
            *(uint4*)&Ksm[row * AQSTR + c8] =
                *(const uint4*)(Kg + (size_t)(s0 + row) * HD + c8);
            *(uint4*)&Vsm[row * AQSTR + c8] =
                *(const uint4*)(Vg + (size_t)(s0 + row) * HD + c8);
        }
        __syncthreads();

        if (s0 > row_max_w) continue;

        // S = Q @ K^T : 4 k-chunks of 16 over D
        float s_[8][4];
#pragma unroll
        for (int j = 0; j < 8; j++)
#pragma unroll
            for (int r = 0; r < 4; r++) s_[j][r] = 0.f;

#pragma unroll
        for (int kc = 0; kc < 4; kc++) {
            uint32_t aq[4];
            ldsm_x4(aq, sQ + q_lane + (uint32_t)(((16 * w) * AQSTR + kc * 16) * 2));
#pragma unroll
            for (int J = 0; J < 4; J++) {
                uint32_t bk[4];
                ldsm_x4(bk, sK + k_lane + (uint32_t)(((16 * J) * AQSTR + kc * 16) * 2));
                mma_f16(s_[2 * J],     aq, bk[0], bk[1]);
                mma_f16(s_[2 * J + 1], aq, bk[2], bk[3]);
            }
        }

        // causal mask
        if (s0 + 63 > q0 + 16 * w) {
#pragma unroll
            for (int j = 0; j < 8; j++) {
                const int c0 = s0 + 8 * j + 2 * tig;
                if (c0 > row_lo)     s_[j][0] = -1e30f;
                if (c0 + 1 > row_lo) s_[j][1] = -1e30f;
                if (c0 > row_hi)     s_[j][2] = -1e30f;
                if (c0 + 1 > row_hi) s_[j][3] = -1e30f;
            }
        }

        // online softmax (rows g / g+8, quad reduction)
        float t_lo = -1e30f, t_hi = -1e30f;
#pragma unroll
        for (int j = 0; j < 8; j++) {
            t_lo = fmaxf(t_lo, fmaxf(s_[j][0], s_[j][1]));
            t_hi = fmaxf(t_hi, fmaxf(s_[j][2], s_[j][3]));
        }
        t_lo = fmaxf(t_lo, __shfl_xor_sync(0xffffffffu, t_lo, 1));
        t_lo = fmaxf(t_lo, __shfl_xor_sync(0xffffffffu, t_lo, 2));
        t_hi = fmaxf(t_hi, __shfl_xor_sync(0xffffffffu, t_hi, 1));
        t_hi = fmaxf(t_hi, __shfl_xor_sync(0xffffffffu, t_hi, 2));

        const float mn_lo = fmaxf(m_lo, t_lo);
        const float mn_hi = fmaxf(m_hi, t_hi);
        const float a_lo = __expf(m_lo - mn_lo);
        const float a_hi = __expf(m_hi - mn_hi);
        m_lo = mn_lo; m_hi = mn_hi;

        float rs_lo = 0.f, rs_hi = 0.f;
#pragma unroll
        for (int j = 0; j < 8; j++) {
            const float p0 = __expf(s_[j][0] - mn_lo);
            const float p1 = __expf(s_[j][1] - mn_lo);
            const float p2 = __expf(s_[j][2] - mn_hi);
            const float p3 = __expf(s_[j][3] - mn_hi);
            rs_lo += p0 + p1;
            rs_hi += p2 + p3;
            // pack P into A-fragment registers (reuse s_ storage)
            s_[j][0] = __uint_as_float(pack_h2(p0, p1));   // row g   pair
            s_[j][1] = __uint_as_float(pack_h2(p2, p3));   // row g+8 pair
        }
        rs_lo += __shfl_xor_sync(0xffffffffu, rs_lo, 1);
        rs_lo += __shfl_xor_sync(0xffffffffu, rs_lo, 2);
        rs_hi += __shfl_xor_sync(0xffffffffu, rs_hi, 1);
        rs_hi += __shfl_xor_sync(0xffffffffu, rs_hi, 2);
        l_lo = l_lo * a_lo + rs_lo;
        l_hi = l_hi * a_hi + rs_hi;

#pragma unroll
        for (int jd = 0; jd < 8; jd++) {
            o[jd][0] *= a_lo; o[jd][1] *= a_lo;
            o[jd][2] *= a_hi; o[jd][3] *= a_hi;
        }

        // O += P @ V : A-frags from packed pairs, V via trans-ldmatrix
#pragma unroll
        for (int sc = 0; sc < 4; sc++) {
            uint32_t a[4];
            a[0] = __float_as_uint(s_[2 * sc][0]);
            a[1] = __float_as_uint(s_[2 * sc][1]);
            a[2] = __float_as_uint(s_[2 * sc + 1][0]);
            a[3] = __float_as_uint(s_[2 * sc + 1][1]);
#pragma unroll
            for (int jd2 = 0; jd2 < 4; jd2++) {
                uint32_t vv[4];
                ldsm_x4_t(vv, sV + v_lane +
                              (uint32_t)(((16 * sc) * AQSTR + jd2 * 16) * 2));
                mma_f16(o[2 * jd2],     a, vv[0], vv[1]);
                mma_f16(o[2 * jd2 + 1], a, vv[2], vv[3]);
            }
        }
    }

    const float il_lo = 1.0f / l_lo;
    const float il_hi = 1.0f / l_hi;
    const int b_ = bh >> 4;
    const int h_ = bh & 15;
    __half* Yb = Y + (size_t)b_ * T_SEQ * C_EMB + h_ * HD;
#pragma unroll
    for (int jd = 0; jd < 8; jd++) {
        const int d = 8 * jd + 2 * tig;
        *(uint32_t*)&Yb[(size_t)row_lo * C_EMB + d] =
            pack_h2(o[jd][0] * il_lo, o[jd][1] * il_lo);
        *(uint32_t*)&Yb[(size_t)row_hi * C_EMB + d] =
            pack_h2(o[jd][2] * il_hi, o[jd][3] * il_hi);
    }
}

// ---------------------------------------------------------------------------
extern "C" void kernel_launch(void* const* d_in, const int* in_sizes, int n_in,
                              void* d_out, int out_size)
{
    const float* x  = (const float*)d_in[0];
    const float* Wq = (const float*)d_in[1];
    const float* bq = (const float*)d_in[2];
    const float* Wk = (const float*)d_in[3];
    const float* bk = (const float*)d_in[4];
    const float* Wv = (const float*)d_in[5];
    const float* bv = (const float*)d_in[6];
    const float* Wp = (const float*)d_in[7];
    const float* bp = (const float*)d_in[8];
    float* out = (float*)d_out;

    __half *Qp, *Kp, *Vp, *Xp, *Yp, *WTp;
    cudaGetSymbolAddress((void**)&Qp, g_Q);
    cudaGetSymbolAddress((void**)&Kp, g_K);
    cudaGetSymbolAddress((void**)&Vp, g_V);
    cudaGetSymbolAddress((void**)&Xp, g_X);
    cudaGetSymbolAddress((void**)&Yp, g_Yatt);
    cudaGetSymbolAddress((void**)&WTp, g_WT);

    cudaFuncSetAttribute(attn_f16_kernel,
                         cudaFuncAttributeMaxDynamicSharedMemorySize, ATTN_SMEM);

    convert_x<<<(M_ROWS * C_EMB) / 1024, 256>>>(x, Xp);
    transpose_w<<<dim3(32, 32, 4), 256>>>(Wq, Wk, Wv, Wp, WTp);

    gemm_qkv<<<dim3(8, 64, 3), 128>>>(Xp, WTp, bq, bk, bv, Qp, Kp, Vp);

    attn_f16_kernel<<<dim3(T_SEQ / 128, BATCH * NH), 256, ATTN_SMEM>>>(Qp, Kp, Vp, Yp);

    gemm_out<<<dim3(8, 64), 128>>>(Yp, WTp, bp, out);
}

// round 17
// speedup vs baseline: 2.2415x; 1.0490x over previous
#include <cuda_runtime.h>
#include <cuda_fp16.h>
#include <cstdint>

#define T_SEQ   2048
#define NH      16
#define HD      64
#define C_EMB   1024
#define BATCH   4
#define M_ROWS  (BATCH * T_SEQ)   // 8192

// Scratch (allocation-free rule: __device__ globals) — all fp16
__device__ __half g_Q[(size_t)M_ROWS * C_EMB];      // Q pre-scaled by 0.125*log2e
__device__ __half g_K[(size_t)M_ROWS * C_EMB];
__device__ __half g_V[(size_t)M_ROWS * C_EMB];
__device__ __half g_X[(size_t)M_ROWS * C_EMB];
__device__ __half g_Yatt[(size_t)M_ROWS * C_EMB];
__device__ __half g_WT[4][(size_t)C_EMB * C_EMB];   // W^T [N][K]

__device__ __forceinline__ uint32_t pack_h2(float lo, float hi) {
    __half2 h = __floats2half2_rn(lo, hi);
    return *reinterpret_cast<uint32_t*>(&h);
}

__device__ __forceinline__ float ex2(float x) {
    float r;
    asm("ex2.approx.ftz.f32 %0, %1;" : "=f"(r) : "f"(x));
    return r;
}

__device__ __forceinline__ void mma_f16(float* c, const uint32_t* a,
                                        uint32_t b0, uint32_t b1) {
    asm volatile(
        "mma.sync.aligned.m16n8k16.row.col.f32.f16.f16.f32 "
        "{%0,%1,%2,%3}, {%4,%5,%6,%7}, {%8,%9}, {%0,%1,%2,%3};"
        : "+f"(c[0]), "+f"(c[1]), "+f"(c[2]), "+f"(c[3])
        : "r"(a[0]), "r"(a[1]), "r"(a[2]), "r"(a[3]), "r"(b0), "r"(b1));
}

__device__ __forceinline__ void ldsm_x4(uint32_t* r, uint32_t addr) {
    asm volatile(
        "ldmatrix.sync.aligned.m8n8.x4.shared.b16 {%0,%1,%2,%3}, [%4];"
        : "=r"(r[0]), "=r"(r[1]), "=r"(r[2]), "=r"(r[3]) : "r"(addr));
}
__device__ __forceinline__ void ldsm_x4_t(uint32_t* r, uint32_t addr) {
    asm volatile(
        "ldmatrix.sync.aligned.m8n8.x4.trans.shared.b16 {%0,%1,%2,%3}, [%4];"
        : "=r"(r[0]), "=r"(r[1]), "=r"(r[2]), "=r"(r[3]) : "r"(addr));
}

__device__ __forceinline__ uint32_t smem_u32(const void* p) {
    return (uint32_t)__cvta_generic_to_shared(p);
}

#define CP_ASYNC16(dst, src) \
    asm volatile("cp.async.ca.shared.global [%0], [%1], 16;" :: "r"(dst), "l"(src) : "memory")
#define CP_COMMIT() asm volatile("cp.async.commit_group;" ::: "memory")
#define CP_WAIT0()  asm volatile("cp.async.wait_group 0;" ::: "memory")

// ---------------------------------------------------------------------------
// x -> half (one pass)
// ---------------------------------------------------------------------------
__global__ __launch_bounds__(256) void convert_x(
    const float* __restrict__ x, __half* __restrict__ o)
{
    const size_t i = ((size_t)blockIdx.x * 256 + threadIdx.x) * 4;
    const float4 v = *(const float4*)(x + i);
    uint2 u;
    u.x = pack_h2(v.x, v.y);
    u.y = pack_h2(v.z, v.w);
    *(uint2*)(o + i) = u;
}

// ---------------------------------------------------------------------------
// Weight transpose + half convert: WT[z][n*K+k] = half(W_z[k*N+n])
// ---------------------------------------------------------------------------
__global__ __launch_bounds__(256) void transpose_w(
    const float* __restrict__ W0, const float* __restrict__ W1,
    const float* __restrict__ W2, const float* __restrict__ W3,
    __half* __restrict__ WT)
{
    __shared__ float tile[32][33];
    const float* W = (blockIdx.z == 0) ? W0 : (blockIdx.z == 1) ? W1
                   : (blockIdx.z == 2) ? W2 : W3;
    __half* out = WT + (size_t)blockIdx.z * C_EMB * C_EMB;

    const int x = threadIdx.x & 31;
    const int y0 = (threadIdx.x >> 5) << 2;
    const int kb = blockIdx.x * 32, nb = blockIdx.y * 32;
#pragma unroll
    for (int i = 0; i < 4; i++)
        tile[y0 + i][x] = W[(size_t)(kb + y0 + i) * C_EMB + nb + x];
    __syncthreads();
#pragma unroll
    for (int i = 0; i < 4; i++)
        out[(size_t)(nb + y0 + i) * C_EMB + kb + x] = __float2half_rn(tile[x][y0 + i]);
}

// ---------------------------------------------------------------------------
// fp16 GEMM: C[M,N] = A[M,K] @ BT[N,K]^T + bias, m16n8k16, fp32 accum.
// 128x128x32 CTA tile, 128 threads (4 warps 2x2), warp tile 64x64.
// MODE 0: float out row-major. MODE 1: half out, scaled, QKV scatter.
// ---------------------------------------------------------------------------
#define BKH 32     // k halves per tile
#define STRH 40    // halves per smem row (32 + 8 pad) = 80 bytes

template <int MODE>
__device__ __forceinline__ void gemm_body(
    const __half* __restrict__ A, const __half* __restrict__ BT,
    const float* __restrict__ bias, float* __restrict__ CoutF,
    __half* __restrict__ CoutH, float scale)
{
    __shared__ __half SA[2][128 * STRH];
    __shared__ __half SB[2][128 * STRH];

    const int tid  = threadIdx.x;
    const int wid  = tid >> 5;
    const int lane = tid & 31;
    const int g    = lane >> 2;
    const int tig  = lane & 3;
    const int bm   = blockIdx.y * 128;
    const int bn   = blockIdx.x * 128;
    const int wm   = (wid & 1) * 64;
    const int wn   = (wid >> 1) * 64;

    const uint32_t sa[2] = { smem_u32(&SA[0][0]), smem_u32(&SA[1][0]) };
    const uint32_t sb[2] = { smem_u32(&SB[0][0]), smem_u32(&SB[1][0]) };
    const uint32_t a_lane = (uint32_t)((lane & 15) * (STRH * 2) + ((lane >> 4) << 4));
    const uint32_t b_lane = (uint32_t)((((lane >> 4) << 3) + (lane & 7)) * (STRH * 2)
                                       + (((lane >> 3) & 1) << 4));

    float acc[4][8][4];
#pragma unroll
    for (int i = 0; i < 4; i++)
#pragma unroll
        for (int j = 0; j < 8; j++)
#pragma unroll
            for (int r = 0; r < 4; r++) acc[i][j][r] = 0.f;

#define ISSUE_TILE(bf, k0)                                                     \
    do {                                                                       \
        _Pragma("unroll")                                                      \
        for (int r = 0; r < 4; r++) {                                          \
            const int idx = tid + r * 128;                                     \
            const int row = idx >> 2;                                          \
            const int ch  = idx & 3;                                           \
            CP_ASYNC16(sa[bf] + (uint32_t)(row * (STRH * 2) + ch * 16),        \
                       A + (size_t)(bm + row) * C_EMB + (k0) + ch * 8);        \
            CP_ASYNC16(sb[bf] + (uint32_t)(row * (STRH * 2) + ch * 16),        \
                       BT + (size_t)(bn + row) * C_EMB + (k0) + ch * 8);       \
        }                                                                      \
    } while (0)

    ISSUE_TILE(0, 0);
    CP_COMMIT();

    const int NCH = C_EMB / BKH;   // 32
    for (int c = 0; c < NCH; c++) {
        const int buf = c & 1;
        CP_WAIT0();
        __syncthreads();
        if (c + 1 < NCH) {
            ISSUE_TILE(buf ^ 1, (c + 1) * BKH);
            CP_COMMIT();
        }

#pragma unroll
        for (int kc = 0; kc < 2; kc++) {
            uint32_t af[4][4], bl[4][4];
#pragma unroll
            for (int i = 0; i < 4; i++)
                ldsm_x4(af[i], sa[buf] + a_lane +
                               (uint32_t)(((wm + 16 * i) * STRH + kc * 16) * 2));
#pragma unroll
            for (int p = 0; p < 4; p++)
                ldsm_x4(bl[p], sb[buf] + b_lane +
                               (uint32_t)(((wn + 16 * p) * STRH + kc * 16) * 2));
#pragma unroll
            for (int i = 0; i < 4; i++)
#pragma unroll
                for (int j = 0; j < 8; j++)
                    mma_f16(acc[i][j], af[i],
                            bl[j >> 1][(j & 1) * 2], bl[j >> 1][(j & 1) * 2 + 1]);
        }
    }
#undef ISSUE_TILE

#pragma unroll
    for (int j = 0; j < 8; j++) {
        const int col = bn + wn + 8 * j + 2 * tig;
        const float b0 = bias[col];
        const float b1 = bias[col + 1];
#pragma unroll
        for (int i = 0; i < 4; i++) {
            const int row = bm + wm + 16 * i + g;
            if (MODE == 0) {
                *(float2*)&CoutF[(size_t)row * C_EMB + col] =
                    make_float2(acc[i][j][0] + b0, acc[i][j][1] + b1);
                *(float2*)&CoutF[(size_t)(row + 8) * C_EMB + col] =
                    make_float2(acc[i][j][2] + b0, acc[i][j][3] + b1);
            } else {
                const uint32_t v0 = pack_h2((acc[i][j][0] + b0) * scale,
                                            (acc[i][j][1] + b1) * scale);
                const uint32_t v1 = pack_h2((acc[i][j][2] + b0) * scale,
                                            (acc[i][j][3] + b1) * scale);
                const int h_ = col >> 6;
                const int d_ = col & (HD - 1);
                const int b0_ = row >> 11;
                const int t0_ = row & (T_SEQ - 1);
                const int b1_ = (row + 8) >> 11;
                const int t1_ = (row + 8) & (T_SEQ - 1);
                *(uint32_t*)&CoutH[(((size_t)b0_ * NH + h_) * T_SEQ + t0_) * HD + d_] = v0;
                *(uint32_t*)&CoutH[(((size_t)b1_ * NH + h_) * T_SEQ + t1_) * HD + d_] = v1;
            }
        }
    }
}

__global__ __launch_bounds__(128) void gemm_qkv(
    const __half* __restrict__ A, const __half* __restrict__ WT,
    const float* __restrict__ c0, const float* __restrict__ c1,
    const float* __restrict__ c2,
    __half* __restrict__ O0, __half* __restrict__ O1, __half* __restrict__ O2)
{
    const int z = blockIdx.z;
    const __half* BT  = WT + (size_t)z * C_EMB * C_EMB;
    const float* bias = (z == 0) ? c0 : (z == 1) ? c1 : c2;
    __half* Cout      = (z == 0) ? O0 : (z == 1) ? O1 : O2;
    // Q carries 1/sqrt(D) * log2(e) so softmax uses bare ex2
    const float scale = (z == 0) ? 0.125f * 1.4426950408889634f : 1.0f;
    gemm_body<1>(A, BT, bias, nullptr, Cout, scale);
}

__global__ __launch_bounds__(128) void gemm_out(
    const __half* __restrict__ A, const __half* __restrict__ WT,
    const float* __restrict__ bias, float* __restrict__ Cout)
{
    gemm_body<0>(A, WT + (size_t)3 * C_EMB * C_EMB, bias, Cout, nullptr, 1.0f);
}

// ---------------------------------------------------------------------------
// fp16 flash attention (m16n8k16, fp32 softmax/accum, causal, base-2 softmax).
// 128 queries/CTA, 128-key staging groups (2x64 subtiles per barrier pair),
// 8 warps x 16 query rows. V via trans-ldmatrix; P via register packs.
// ---------------------------------------------------------------------------
#define AQSTR 72   // halves per row (64 + 8) = 144 B
#define ATTN_SMEM ((128 * AQSTR + 128 * AQSTR + 128 * AQSTR) * 2)   // 55296 B

__global__ __launch_bounds__(256, 2) void attn_f16_kernel(
    const __half* __restrict__ Q, const __half* __restrict__ K,
    const __half* __restrict__ V, __half* __restrict__ Y)
{
    extern __shared__ __half smh[];
    __half* Qsm = smh;                     // [128][72]
    __half* Ksm = smh + 128 * AQSTR;       // [128][72]
    __half* Vsm = Ksm + 128 * AQSTR;       // [128][72]
    const uint32_t sQ = smem_u32(Qsm);
    const uint32_t sK = smem_u32(Ksm);
    const uint32_t sV = smem_u32(Vsm);

    const int tid  = threadIdx.x;
    const int w    = tid >> 5;
    const int lane = tid & 31;
    const int g    = lane >> 2;
    const int tig  = lane & 3;
    const int bh   = blockIdx.y;
    const int qb   = blockIdx.x;
    const int q0   = qb * 128;

    const __half* Qg = Q + ((size_t)bh * T_SEQ + q0) * HD;
    const __half* Kg = K + (size_t)bh * T_SEQ * HD;
    const __half* Vg = V + (size_t)bh * T_SEQ * HD;

    const uint32_t q_lane = (uint32_t)((lane & 15) * (AQSTR * 2) + ((lane >> 4) << 4));
    const uint32_t k_lane = (uint32_t)((((lane >> 4) << 3) + (lane & 7)) * (AQSTR * 2)
                                       + (((lane >> 3) & 1) << 4));
    const uint32_t v_lane = (uint32_t)(((((lane >> 3) & 1) << 3) + (lane & 7)) * (AQSTR * 2)
                                       + ((lane >> 4) << 4));

    // Stage Q
#pragma unroll
    for (int r = 0; r < 4; r++) {
        const int idx = tid + r * 256;
        const int row = idx >> 3;
        const int c8  = (idx & 7) << 3;
        *(uint4*)&Qsm[row * AQSTR + c8] = *(const uint4*)(Qg + (size_t)row * HD + c8);
    }

    float o[8][4];
#pragma unroll
    for (int j = 0; j < 8; j++)
#pragma unroll
        for (int r = 0; r < 4; r++) o[j][r] = 0.f;
    float m_lo = -1e30f, m_hi = -1e30f, l_lo = 0.f, l_hi = 0.f;

    const int row_lo  = q0 + 16 * w + g;
    const int row_hi  = row_lo + 8;
    const int row_max_w = q0 + 16 * w + 15;

    // 128-key staging groups
    for (int t0 = 0; t0 < q0 + 128; t0 += 128) {
        __syncthreads();
#pragma unroll
        for (int r = 0; r < 4; r++) {
            const int idx = tid + r * 256;   // 1024 chunks: 128 rows x 8
            const int row = idx >> 3;
            const int c8  = (idx & 7) << 3;
            *(uint4*)&Ksm[row * AQSTR + c8] =
                *(const uint4*)(Kg + (size_t)(t0 + row) * HD + c8);
            *(uint4*)&Vsm[row * AQSTR + c8] =
                *(const uint4*)(Vg + (size_t)(t0 + row) * HD + c8);
        }
        __syncthreads();

#pragma unroll
        for (int hf = 0; hf < 2; hf++) {
            const int s0 = t0 + 64 * hf;
            if (s0 > row_max_w) continue;
            const uint32_t kvoff = (uint32_t)(64 * hf * AQSTR * 2);

            // S = Q @ K^T
            float s_[8][4];
#pragma unroll
            for (int j = 0; j < 8; j++)
#pragma unroll
                for (int r = 0; r < 4; r++) s_[j][r] = 0.f;

#pragma unroll
            for (int kc = 0; kc < 4; kc++) {
                uint32_t aq[4];
                ldsm_x4(aq, sQ + q_lane + (uint32_t)(((16 * w) * AQSTR + kc * 16) * 2));
#pragma unroll
                for (int J = 0; J < 4; J++) {
                    uint32_t bk[4];
                    ldsm_x4(bk, sK + kvoff + k_lane +
                                (uint32_t)(((16 * J) * AQSTR + kc * 16) * 2));
                    mma_f16(s_[2 * J],     aq, bk[0], bk[1]);
                    mma_f16(s_[2 * J + 1], aq, bk[2], bk[3]);
                }
            }

            // causal mask
            if (s0 + 63 > q0 + 16 * w) {
#pragma unroll
                for (int j = 0; j < 8; j++) {
                    const int c0 = s0 + 8 * j + 2 * tig;
                    if (c0 > row_lo)     s_[j][0] = -1e30f;
                    if (c0 + 1 > row_lo) s_[j][1] = -1e30f;
                    if (c0 > row_hi)     s_[j][2] = -1e30f;
                    if (c0 + 1 > row_hi) s_[j][3] = -1e30f;
                }
            }

            // online softmax in base-2 (Q pre-scaled by log2e/8)
            float t_lo = -1e30f, t_hi = -1e30f;
#pragma unroll
            for (int j = 0; j < 8; j++) {
                t_lo = fmaxf(t_lo, fmaxf(s_[j][0], s_[j][1]));
                t_hi = fmaxf(t_hi, fmaxf(s_[j][2], s_[j][3]));
            }
            t_lo = fmaxf(t_lo, __shfl_xor_sync(0xffffffffu, t_lo, 1));
            t_lo = fmaxf(t_lo, __shfl_xor_sync(0xffffffffu, t_lo, 2));
            t_hi = fmaxf(t_hi, __shfl_xor_sync(0xffffffffu, t_hi, 1));
            t_hi = fmaxf(t_hi, __shfl_xor_sync(0xffffffffu, t_hi, 2));

            const float mn_lo = fmaxf(m_lo, t_lo);
            const float mn_hi = fmaxf(m_hi, t_hi);
            const float a_lo = ex2(m_lo - mn_lo);
            const float a_hi = ex2(m_hi - mn_hi);
            m_lo = mn_lo; m_hi = mn_hi;

            float rs_lo = 0.f, rs_hi = 0.f;
#pragma unroll
            for (int j = 0; j < 8; j++) {
                const float p0 = ex2(s_[j][0] - mn_lo);
                const float p1 = ex2(s_[j][1] - mn_lo);
                const float p2 = ex2(s_[j][2] - mn_hi);
                const float p3 = ex2(s_[j][3] - mn_hi);
                rs_lo += p0 + p1;
                rs_hi += p2 + p3;
                s_[j][0] = __uint_as_float(pack_h2(p0, p1));
                s_[j][1] = __uint_as_float(pack_h2(p2, p3));
            }
            rs_lo += __shfl_xor_sync(0xffffffffu, rs_lo, 1);
            rs_lo += __shfl_xor_sync(0xffffffffu, rs_lo, 2);
            rs_hi += __shfl_xor_sync(0xffffffffu, rs_hi, 1);
            rs_hi += __shfl_xor_sync(0xffffffffu, rs_hi, 2);
            l_lo = l_lo * a_lo + rs_lo;
            l_hi = l_hi * a_hi + rs_hi;

#pragma unroll
            for (int jd = 0; jd < 8; jd++) {
                o[jd][0] *= a_lo; o[jd][1] *= a_lo;
                o[jd][2] *= a_hi; o[jd][3] *= a_hi;
            }

            // O += P @ V
#pragma unroll
            for (int sc = 0; sc < 4; sc++) {
                uint32_t a[4];
                a[0] = __float_as_uint(s_[2 * sc][0]);
                a[1] = __float_as_uint(s_[2 * sc][1]);
                a[2] = __float_as_uint(s_[2 * sc + 1][0]);
                a[3] = __float_as_uint(s_[2 * sc + 1][1]);
#pragma unroll
                for (int jd2 = 0; jd2 < 4; jd2++) {
                    uint32_t vv[4];
                    ldsm_x4_t(vv, sV + kvoff + v_lane +
                                  (uint32_t)(((16 * sc) * AQSTR + jd2 * 16) * 2));
                    mma_f16(o[2 * jd2],     a, vv[0], vv[1]);
                    mma_f16(o[2 * jd2 + 1], a, vv[2], vv[3]);
                }
            }
        }
    }

    const float il_lo = 1.0f / l_lo;
    const float il_hi = 1.0f / l_hi;
    const int b_ = bh >> 4;
    const int h_ = bh & 15;
    __half* Yb = Y + (size_t)b_ * T_SEQ * C_EMB + h_ * HD;
#pragma unroll
    for (int jd = 0; jd < 8; jd++) {
        const int d = 8 * jd + 2 * tig;
        *(uint32_t*)&Yb[(size_t)row_lo * C_EMB + d] =
            pack_h2(o[jd][0] * il_lo, o[jd][1] * il_lo);
        *(uint32_t*)&Yb[(size_t)row_hi * C_EMB + d] =
            pack_h2(o[jd][2] * il_hi, o[jd][3] * il_hi);
    }
}

// ---------------------------------------------------------------------------
extern "C" void kernel_launch(void* const* d_in, const int* in_sizes, int n_in,
                              void* d_out, int out_size)
{
    const float* x  = (const float*)d_in[0];
    const float* Wq = (const float*)d_in[1];
    const float* bq = (const float*)d_in[2];
    const float* Wk = (const float*)d_in[3];
    const float* bk = (const float*)d_in[4];
    const float* Wv = (const float*)d_in[5];
    const float* bv = (const float*)d_in[6];
    const float* Wp = (const float*)d_in[7];
    const float* bp = (const float*)d_in[8];
    float* out = (float*)d_out;

    __half *Qp, *Kp, *Vp, *Xp, *Yp, *WTp;
    cudaGetSymbolAddress((void**)&Qp, g_Q);
    cudaGetSymbolAddress((void**)&Kp, g_K);
    cudaGetSymbolAddress((void**)&Vp, g_V);
    cudaGetSymbolAddress((void**)&Xp, g_X);
    cudaGetSymbolAddress((void**)&Yp, g_Yatt);
    cudaGetSymbolAddress((void**)&WTp, g_WT);

    cudaFuncSetAttribute(attn_f16_kernel,
                         cudaFuncAttributeMaxDynamicSharedMemorySize, ATTN_SMEM);

    convert_x<<<(M_ROWS * C_EMB) / 1024, 256>>>(x, Xp);
    transpose_w<<<dim3(32, 32, 4), 256>>>(Wq, Wk, Wv, Wp, WTp);

    gemm_qkv<<<dim3(8, 64, 3), 128>>>(Xp, WTp, bq, bk, bv, Qp, Kp, Vp);

    attn_f16_kernel<<<dim3(T_SEQ / 128, BATCH * NH), 256, ATTN_SMEM>>>(Qp, Kp, Vp, Yp);

    gemm_out<<<dim3(8, 64), 128>>>(Yp, WTp, bp, out);
}